// round 12
// baseline (speedup 1.0000x reference)
#include <cuda_runtime.h>
#include <math.h>

// ---------------------------------------------------------------------------
// Mamba forward, fused pipeline:
//   G1: proj = x @ W_in^T                      (2048 x 4096, K=1024)
//   G2: ssm  = hidden @ W_x^T                  (2048 x 96,   K=2048)
//   G3: dt   = softplus(ssm[:, :64] @ W_dt^T + b)  (2048 x 2048, K=64)
//   S : fwd/bwd first-order recurrences over L, reduced over n=16 via shfl
//   T : gating + transpose -> scan_out (2048 x 2048)
//   G4: out  = scan_out @ W_out^T              (2048 x 1024, K=2048)
// All GEMMs are "NT": C[m,n] = sum_k A[m,k]*B[n,k], both K-major.
// ---------------------------------------------------------------------------

#define BM 128
#define BN 128
#define BKK 8
#define TM 8
#define TN 8

// Scratch (static __device__: allocation-free per harness rules)
__device__ float g_proj[2048u*4096u];   // (b*l, 4096): hidden | gate
__device__ float g_ssm [2048u*96u];     // (b*l, 96): dt_in(64) | B(16) | C(16)
__device__ float g_dt  [2048u*2048u];   // (b*l, d) post-softplus
__device__ float g_yf  [2u*2048u*1024u];// (b, d, l)
__device__ float g_yb  [2u*2048u*1024u];// (b, d, l)
__device__ float g_so  [2048u*2048u];   // (b*l, d) gated scan output

// ---------------------------------------------------------------------------
// NT GEMM, 128x128 block tile, 8x8 per-thread tile, 256 threads.
// Double-buffered smem + register prefetch: one __syncthreads per K-step.
// EPI==1: fused bias + softplus epilogue. N may be ragged (predicated).
// ---------------------------------------------------------------------------
template<int EPI>
__global__ __launch_bounds__(256)
void gemm_nt(const float* __restrict__ A, int lda,
             const float* __restrict__ B, int ldb,
             float* __restrict__ C, int ldc,
             int N, int K, const float* __restrict__ bias)
{
    __shared__ float As[2][BKK*BM];
    __shared__ float Bs[2][BKK*BN];
    const int tid = threadIdx.x;
    const int bm  = blockIdx.y, bn = blockIdx.x;

    const int ldRow = tid >> 1;          // 0..127
    const int ldCol = (tid & 1) * 4;     // 0 or 4 (float4 within BK=8)
    const float* Aptr = A + (size_t)(bm*BM + ldRow)*lda + ldCol;
    const int bRowG = bn*BN + ldRow;
    const float* Bptr = B + (size_t)bRowG*ldb + ldCol;
    const bool bValid = bRowG < N;

    const int tr = tid >> 4, tc = tid & 15;
    const int m0 = tr*TM, n0 = tc*TN;

    float acc[TM][TN];
    #pragma unroll
    for (int i = 0; i < TM; i++)
        #pragma unroll
        for (int j = 0; j < TN; j++) acc[i][j] = 0.f;

    const int nT = K / BKK;

    // Preload tile 0 into buffer 0
    {
        float4 av = *(const float4*)(Aptr);
        float4 bv = bValid ? *(const float4*)(Bptr)
                           : make_float4(0.f, 0.f, 0.f, 0.f);
        As[0][(ldCol+0)*BM + ldRow] = av.x;
        As[0][(ldCol+1)*BM + ldRow] = av.y;
        As[0][(ldCol+2)*BM + ldRow] = av.z;
        As[0][(ldCol+3)*BM + ldRow] = av.w;
        Bs[0][(ldCol+0)*BN + ldRow] = bv.x;
        Bs[0][(ldCol+1)*BN + ldRow] = bv.y;
        Bs[0][(ldCol+2)*BN + ldRow] = bv.z;
        Bs[0][(ldCol+3)*BN + ldRow] = bv.w;
    }
    __syncthreads();

    int buf = 0;
    for (int t = 0; t < nT; t++) {
        // Prefetch next tile into registers (overlaps with compute below)
        float4 av2, bv2;
        const bool hasNext = (t + 1 < nT);
        if (hasNext) {
            int k0 = (t + 1) * BKK;
            av2 = *(const float4*)(Aptr + k0);
            bv2 = bValid ? *(const float4*)(Bptr + k0)
                         : make_float4(0.f, 0.f, 0.f, 0.f);
        }

        #pragma unroll
        for (int k = 0; k < BKK; k++) {
            float4 a0 = *(const float4*)(&As[buf][k*BM + m0]);
            float4 a1 = *(const float4*)(&As[buf][k*BM + m0 + 4]);
            float4 b0 = *(const float4*)(&Bs[buf][k*BN + n0]);
            float4 b1 = *(const float4*)(&Bs[buf][k*BN + n0 + 4]);
            float ra[TM] = {a0.x,a0.y,a0.z,a0.w,a1.x,a1.y,a1.z,a1.w};
            float rb[TN] = {b0.x,b0.y,b0.z,b0.w,b1.x,b1.y,b1.z,b1.w};
            #pragma unroll
            for (int i = 0; i < TM; i++)
                #pragma unroll
                for (int j = 0; j < TN; j++)
                    acc[i][j] = fmaf(ra[i], rb[j], acc[i][j]);
        }

        if (hasNext) {
            int nb = buf ^ 1;
            As[nb][(ldCol+0)*BM + ldRow] = av2.x;
            As[nb][(ldCol+1)*BM + ldRow] = av2.y;
            As[nb][(ldCol+2)*BM + ldRow] = av2.z;
            As[nb][(ldCol+3)*BM + ldRow] = av2.w;
            Bs[nb][(ldCol+0)*BN + ldRow] = bv2.x;
            Bs[nb][(ldCol+1)*BN + ldRow] = bv2.y;
            Bs[nb][(ldCol+2)*BN + ldRow] = bv2.z;
            Bs[nb][(ldCol+3)*BN + ldRow] = bv2.w;
            __syncthreads();
        }
        buf ^= 1;
    }

    #pragma unroll
    for (int i = 0; i < TM; i++) {
        int cm = bm*BM + m0 + i;
        #pragma unroll
        for (int j = 0; j < TN; j++) {
            int cn = bn*BN + n0 + j;
            if (cn < N) {
                float v = acc[i][j];
                if (EPI == 1) {
                    v += bias[cn];
                    v = (v > 20.f) ? v : log1pf(__expf(v));  // softplus
                }
                C[(size_t)cm*ldc + cn] = v;
            }
        }
    }
}

// ---------------------------------------------------------------------------
// Selective scan: warp = 2 channels (d, d+1) x 16 states (n).
// Grid covers {fwd, bwd} x b x 1024 d-pairs = 4096 warps.
//   fwd: h_t = a_t h_{t-1} + u_t;                  yf[t] = sum_n h_t * C[t,n]
//   bwd: h_t = a_{t+1} h_{t+1} + u_t  (a index shifted by +1, since
//        a_rev = roll(flip(a),1) => multiplier between t and t+1 is a_{t+1});
//        yb[t] = sum_n (h_t - u_t) * C[t,n]
// Final y = 1.3*(yf+yb) matches (fwd + bwd - u)*1.3 dotted with C.
// ---------------------------------------------------------------------------
__global__ __launch_bounds__(256)
void scan_kernel(const float* __restrict__ A_log)
{
    const int w    = (blockIdx.x * 256 + threadIdx.x) >> 5;
    const int lane = threadIdx.x & 31;
    const int dir  = w >> 11;          // 0 = fwd, 1 = bwd
    const int rem  = w & 2047;
    const int b    = rem >> 10;
    const int dpair= rem & 1023;
    const int half = lane >> 4;
    const int n    = lane & 15;
    const int d    = dpair*2 + half;

    const float An = -__expf(A_log[d*16 + n]);   // A[d,n]
    float h = 0.f;
    float a_prev = 0.f;   // bwd: decay between t and t+1 is a_{t+1}

    float* yout = (dir ? g_yb : g_yf) + ((size_t)b*2048 + d) * 1024;
    const float* dtp = g_dt  + (size_t)b*1024*2048 + d;
    const float* xp  = g_proj+ (size_t)b*1024*4096 + d;          // hidden
    const float* bp  = g_ssm + (size_t)b*1024*96 + 64 + n;       // B[t,n]
    const float* cp  = bp + 16;                                  // C[t,n]

    for (int i = 0; i < 1024; i++) {
        int t = dir ? (1023 - i) : i;
        float dtv = dtp[(size_t)t*2048];
        float x   = xp [(size_t)t*4096];
        float Bv  = bp [t*96];
        float Cv  = cp [t*96];
        float a = __expf(An * dtv);
        float u = dtv * Bv * x;
        float p;
        if (dir) {
            h = fmaf(a_prev, h, u);   // uses a_{t+1} from previous iteration
            a_prev = a;
            p = (h - u) * Cv;
        } else {
            h = fmaf(a, h, u);
            p = h * Cv;
        }
        p += __shfl_xor_sync(0xffffffffu, p, 8);
        p += __shfl_xor_sync(0xffffffffu, p, 4);
        p += __shfl_xor_sync(0xffffffffu, p, 2);
        p += __shfl_xor_sync(0xffffffffu, p, 1);
        if (n == 0) yout[t] = p;
    }
}

// ---------------------------------------------------------------------------
// Gating + transpose: read y (b,d,l), write scan_out (b*l, d).
// scan_out = (1.3*(yf+yb) + hidden*D) * silu(gate)
// ---------------------------------------------------------------------------
__global__ __launch_bounds__(1024)
void gate_kernel(const float* __restrict__ Dv)
{
    __shared__ float s[32][33];
    const int b  = blockIdx.z;
    const int d0 = blockIdx.y * 32;
    const int l0 = blockIdx.x * 32;
    const int tx = threadIdx.x, ty = threadIdx.y;

    size_t src = ((size_t)b*2048 + d0 + ty)*1024 + l0 + tx;   // (d, l)
    s[ty][tx] = 1.3f * (g_yf[src] + g_yb[src]);
    __syncthreads();

    const int l = l0 + ty, d = d0 + tx;
    const size_t r = (size_t)b*1024 + l;
    float x = g_proj[r*4096 + d];
    float g = g_proj[r*4096 + 2048 + d];
    float y = s[tx][ty];
    float sil = g / (1.f + __expf(-g));
    g_so[r*2048 + d] = (y + x * Dv[d]) * sil;
}

// ---------------------------------------------------------------------------
extern "C" void kernel_launch(void* const* d_in, const int* in_sizes, int n_in,
                              void* d_out, int out_size)
{
    (void)in_sizes; (void)n_in; (void)out_size;
    const float* x     = (const float*)d_in[0];  // (2,1024,1024)
    const float* w_in  = (const float*)d_in[1];  // (4096,1024)
    const float* w_x   = (const float*)d_in[2];  // (96,2048)
    const float* w_dt  = (const float*)d_in[3];  // (2048,64)
    const float* b_dt  = (const float*)d_in[4];  // (2048,)
    const float* A_log = (const float*)d_in[5];  // (2048,16)
    const float* Dv    = (const float*)d_in[6];  // (2048,)
    const float* w_out = (const float*)d_in[7];  // (1024,2048)
    float* out = (float*)d_out;                  // (2,1024,1024)

    float *proj, *ssm, *dtb, *so;
    cudaGetSymbolAddress((void**)&proj, g_proj);
    cudaGetSymbolAddress((void**)&ssm,  g_ssm);
    cudaGetSymbolAddress((void**)&dtb,  g_dt);
    cudaGetSymbolAddress((void**)&so,   g_so);

    // G1: proj = x @ W_in^T
    gemm_nt<0><<<dim3(32, 16), 256>>>(x, 1024, w_in, 1024, proj, 4096,
                                      4096, 1024, nullptr);
    // G2: ssm = hidden @ W_x^T  (hidden = proj[:, :2048], lda=4096)
    gemm_nt<0><<<dim3(1, 16), 256>>>(proj, 4096, w_x, 2048, ssm, 96,
                                     96, 2048, nullptr);
    // G3: dt = softplus(ssm[:, :64] @ W_dt^T + b)
    gemm_nt<1><<<dim3(16, 16), 256>>>(ssm, 96, w_dt, 64, dtb, 2048,
                                      2048, 64, b_dt);
    // S: fwd + bwd recurrences (concurrent grid halves)
    scan_kernel<<<512, 256>>>(A_log);
    // T: gating + transpose
    gate_kernel<<<dim3(32, 64, 2), dim3(32, 32)>>>(Dv);
    // G4: out = scan_out @ W_out^T
    gemm_nt<0><<<dim3(8, 16), 256>>>(so, 2048, w_out, 2048, out, 1024,
                                     1024, 2048, nullptr);
}

// round 14
// speedup vs baseline: 1.2555x; 1.2555x over previous
#include <cuda_runtime.h>
#include <cuda_bf16.h>
#include <math.h>

// ---------------------------------------------------------------------------
// Mamba forward:
//   G1: proj = x @ W_in^T         (2048 x 4096, K=1024)  [split-bf16 mma]
//   G2: ssm  = hidden @ W_x^T     (2048 x 96,   K=2048)  [SIMT]
//   G3: dt   = softplus(...)      (2048 x 2048, K=64)    [SIMT]
//   S : fwd/bwd recurrences (software-pipelined)
//   T : gating + transpose
//   G4: out  = scan_out @ W_out^T (2048 x 1024, K=2048)  [split-bf16 mma]
// ---------------------------------------------------------------------------

#define BM 128
#define BN 128
#define BKK 8
#define TM 8
#define TN 8

__device__ float g_proj[2048u*4096u];
__device__ float g_ssm [2048u*96u];
__device__ float g_dt  [2048u*2048u];
__device__ float g_yf  [2u*2048u*1024u];
__device__ float g_yb  [2u*2048u*1024u];
__device__ float g_so  [2048u*2048u];

// ---------------------------------------------------------------------------
// SIMT NT GEMM (kept for G2 ragged-N and G3 small-K + softplus epilogue)
// ---------------------------------------------------------------------------
template<int EPI>
__global__ __launch_bounds__(256)
void gemm_nt(const float* __restrict__ A, int lda,
             const float* __restrict__ B, int ldb,
             float* __restrict__ C, int ldc,
             int N, int K, const float* __restrict__ bias)
{
    __shared__ float As[2][BKK*BM];
    __shared__ float Bs[2][BKK*BN];
    const int tid = threadIdx.x;
    const int bm  = blockIdx.y, bn = blockIdx.x;

    const int ldRow = tid >> 1;
    const int ldCol = (tid & 1) * 4;
    const float* Aptr = A + (size_t)(bm*BM + ldRow)*lda + ldCol;
    const int bRowG = bn*BN + ldRow;
    const float* Bptr = B + (size_t)bRowG*ldb + ldCol;
    const bool bValid = bRowG < N;

    const int tr = tid >> 4, tc = tid & 15;
    const int m0 = tr*TM, n0 = tc*TN;

    float acc[TM][TN];
    #pragma unroll
    for (int i = 0; i < TM; i++)
        #pragma unroll
        for (int j = 0; j < TN; j++) acc[i][j] = 0.f;

    const int nT = K / BKK;
    {
        float4 av = *(const float4*)(Aptr);
        float4 bv = bValid ? *(const float4*)(Bptr) : make_float4(0.f,0.f,0.f,0.f);
        As[0][(ldCol+0)*BM + ldRow] = av.x;
        As[0][(ldCol+1)*BM + ldRow] = av.y;
        As[0][(ldCol+2)*BM + ldRow] = av.z;
        As[0][(ldCol+3)*BM + ldRow] = av.w;
        Bs[0][(ldCol+0)*BN + ldRow] = bv.x;
        Bs[0][(ldCol+1)*BN + ldRow] = bv.y;
        Bs[0][(ldCol+2)*BN + ldRow] = bv.z;
        Bs[0][(ldCol+3)*BN + ldRow] = bv.w;
    }
    __syncthreads();

    int buf = 0;
    for (int t = 0; t < nT; t++) {
        float4 av2, bv2;
        const bool hasNext = (t + 1 < nT);
        if (hasNext) {
            int k0 = (t + 1) * BKK;
            av2 = *(const float4*)(Aptr + k0);
            bv2 = bValid ? *(const float4*)(Bptr + k0) : make_float4(0.f,0.f,0.f,0.f);
        }
        #pragma unroll
        for (int k = 0; k < BKK; k++) {
            float4 a0 = *(const float4*)(&As[buf][k*BM + m0]);
            float4 a1 = *(const float4*)(&As[buf][k*BM + m0 + 4]);
            float4 b0 = *(const float4*)(&Bs[buf][k*BN + n0]);
            float4 b1 = *(const float4*)(&Bs[buf][k*BN + n0 + 4]);
            float ra[TM] = {a0.x,a0.y,a0.z,a0.w,a1.x,a1.y,a1.z,a1.w};
            float rb[TN] = {b0.x,b0.y,b0.z,b0.w,b1.x,b1.y,b1.z,b1.w};
            #pragma unroll
            for (int i = 0; i < TM; i++)
                #pragma unroll
                for (int j = 0; j < TN; j++)
                    acc[i][j] = fmaf(ra[i], rb[j], acc[i][j]);
        }
        if (hasNext) {
            int nb = buf ^ 1;
            As[nb][(ldCol+0)*BM + ldRow] = av2.x;
            As[nb][(ldCol+1)*BM + ldRow] = av2.y;
            As[nb][(ldCol+2)*BM + ldRow] = av2.z;
            As[nb][(ldCol+3)*BM + ldRow] = av2.w;
            Bs[nb][(ldCol+0)*BN + ldRow] = bv2.x;
            Bs[nb][(ldCol+1)*BN + ldRow] = bv2.y;
            Bs[nb][(ldCol+2)*BN + ldRow] = bv2.z;
            Bs[nb][(ldCol+3)*BN + ldRow] = bv2.w;
            __syncthreads();
        }
        buf ^= 1;
    }

    #pragma unroll
    for (int i = 0; i < TM; i++) {
        int cm = bm*BM + m0 + i;
        #pragma unroll
        for (int j = 0; j < TN; j++) {
            int cn = bn*BN + n0 + j;
            if (cn < N) {
                float v = acc[i][j];
                if (EPI == 1) {
                    v += bias[cn];
                    v = (v > 20.f) ? v : log1pf(__expf(v));
                }
                C[(size_t)cm*ldc + cn] = v;
            }
        }
    }
}

// ---------------------------------------------------------------------------
// Split-bf16 tensor-core NT GEMM for G1/G4 (M mult of 128, N mult of 64,
// K mult of 32). C = Ah·Bh + Ah·Bl + Al·Bh where X = Xh + Xl (bf16 pair).
// Tile: BM2=128, BN2=64, BK2=32; 8 warps, warp tile 32x32, mma m16n8k16.
// ---------------------------------------------------------------------------
#define BM2 128
#define BN2 64
#define BK2 32
#define BKP 40   // padded row stride in bf16 elems (80B: conflict-free)

__device__ __forceinline__ void mma_bf16(float& c0, float& c1, float& c2, float& c3,
                                         unsigned a0, unsigned a1, unsigned a2, unsigned a3,
                                         unsigned b0, unsigned b1)
{
    asm volatile(
        "mma.sync.aligned.m16n8k16.row.col.f32.bf16.bf16.f32 "
        "{%0,%1,%2,%3}, {%4,%5,%6,%7}, {%8,%9}, {%0,%1,%2,%3};"
        : "+f"(c0), "+f"(c1), "+f"(c2), "+f"(c3)
        : "r"(a0), "r"(a1), "r"(a2), "r"(a3), "r"(b0), "r"(b1));
}

__global__ __launch_bounds__(256)
void gemm_nt_bfsplit(const float* __restrict__ A, int lda,
                     const float* __restrict__ B, int ldb,
                     float* __restrict__ C, int ldc, int K)
{
    __shared__ __nv_bfloat16 Ah[BM2][BKP], Al[BM2][BKP];
    __shared__ __nv_bfloat16 Bh[BN2][BKP], Bl[BN2][BKP];

    const int tid  = threadIdx.x;
    const int bm   = blockIdx.y, bn = blockIdx.x;
    const int warp = tid >> 5, lane = tid & 31;
    const int g    = lane >> 2, t4 = lane & 3;     // mma group / thread-in-group
    const int wm   = (warp >> 1) * 32;             // warp m offset (0,32,64,96)
    const int wn   = (warp & 1) * 32;              // warp n offset (0,32)

    float acc1[2][4][4], acc2[2][4][4];
    #pragma unroll
    for (int mi = 0; mi < 2; mi++)
        #pragma unroll
        for (int nj = 0; nj < 4; nj++)
            #pragma unroll
            for (int r = 0; r < 4; r++) { acc1[mi][nj][r] = 0.f; acc2[mi][nj][r] = 0.f; }

    for (int k0 = 0; k0 < K; k0 += BK2) {
        // Load + split-convert A tile (128x32 fp32 -> hi/lo bf16)
        #pragma unroll
        for (int j = 0; j < 4; j++) {                 // 1024 float4 / 256 thr
            int lin = tid + j*256;
            int row = lin >> 3, c4 = (lin & 7) * 4;
            float4 v = *(const float4*)(A + (size_t)(bm*BM2 + row)*lda + k0 + c4);
            float vs[4] = {v.x, v.y, v.z, v.w};
            #pragma unroll
            for (int e = 0; e < 4; e++) {
                __nv_bfloat16 h = __float2bfloat16(vs[e]);
                Ah[row][c4+e] = h;
                Al[row][c4+e] = __float2bfloat16(vs[e] - __bfloat162float(h));
            }
        }
        // Load + split-convert B tile (64x32)
        #pragma unroll
        for (int j = 0; j < 2; j++) {                 // 512 float4 / 256 thr
            int lin = tid + j*256;
            int row = lin >> 3, c4 = (lin & 7) * 4;
            float4 v = *(const float4*)(B + (size_t)(bn*BN2 + row)*ldb + k0 + c4);
            float vs[4] = {v.x, v.y, v.z, v.w};
            #pragma unroll
            for (int e = 0; e < 4; e++) {
                __nv_bfloat16 h = __float2bfloat16(vs[e]);
                Bh[row][c4+e] = h;
                Bl[row][c4+e] = __float2bfloat16(vs[e] - __bfloat162float(h));
            }
        }
        __syncthreads();

        #pragma unroll
        for (int kk = 0; kk < BK2; kk += 16) {
            unsigned ah[2][4], al[2][4], bh[4][2], bl[4][2];
            #pragma unroll
            for (int mi = 0; mi < 2; mi++) {
                int r0 = wm + mi*16 + g;
                ah[mi][0] = *(const unsigned*)&Ah[r0    ][kk + 2*t4    ];
                ah[mi][1] = *(const unsigned*)&Ah[r0 + 8][kk + 2*t4    ];
                ah[mi][2] = *(const unsigned*)&Ah[r0    ][kk + 2*t4 + 8];
                ah[mi][3] = *(const unsigned*)&Ah[r0 + 8][kk + 2*t4 + 8];
                al[mi][0] = *(const unsigned*)&Al[r0    ][kk + 2*t4    ];
                al[mi][1] = *(const unsigned*)&Al[r0 + 8][kk + 2*t4    ];
                al[mi][2] = *(const unsigned*)&Al[r0    ][kk + 2*t4 + 8];
                al[mi][3] = *(const unsigned*)&Al[r0 + 8][kk + 2*t4 + 8];
            }
            #pragma unroll
            for (int nj = 0; nj < 4; nj++) {
                int r0 = wn + nj*8 + g;
                bh[nj][0] = *(const unsigned*)&Bh[r0][kk + 2*t4    ];
                bh[nj][1] = *(const unsigned*)&Bh[r0][kk + 2*t4 + 8];
                bl[nj][0] = *(const unsigned*)&Bl[r0][kk + 2*t4    ];
                bl[nj][1] = *(const unsigned*)&Bl[r0][kk + 2*t4 + 8];
            }
            #pragma unroll
            for (int mi = 0; mi < 2; mi++)
                #pragma unroll
                for (int nj = 0; nj < 4; nj++) {
                    mma_bf16(acc1[mi][nj][0], acc1[mi][nj][1], acc1[mi][nj][2], acc1[mi][nj][3],
                             ah[mi][0], ah[mi][1], ah[mi][2], ah[mi][3], bh[nj][0], bh[nj][1]);
                    mma_bf16(acc2[mi][nj][0], acc2[mi][nj][1], acc2[mi][nj][2], acc2[mi][nj][3],
                             ah[mi][0], ah[mi][1], ah[mi][2], ah[mi][3], bl[nj][0], bl[nj][1]);
                    mma_bf16(acc2[mi][nj][0], acc2[mi][nj][1], acc2[mi][nj][2], acc2[mi][nj][3],
                             al[mi][0], al[mi][1], al[mi][2], al[mi][3], bh[nj][0], bh[nj][1]);
                }
        }
        __syncthreads();
    }

    // Epilogue: c0,c1 -> (row g, cols 2t,2t+1); c2,c3 -> (row g+8)
    #pragma unroll
    for (int mi = 0; mi < 2; mi++) {
        int rBase = bm*BM2 + wm + mi*16 + g;
        #pragma unroll
        for (int nj = 0; nj < 4; nj++) {
            int cBase = bn*BN2 + wn + nj*8 + 2*t4;
            float v0 = acc1[mi][nj][0] + acc2[mi][nj][0];
            float v1 = acc1[mi][nj][1] + acc2[mi][nj][1];
            float v2 = acc1[mi][nj][2] + acc2[mi][nj][2];
            float v3 = acc1[mi][nj][3] + acc2[mi][nj][3];
            C[(size_t)rBase*ldc + cBase]       = v0;
            C[(size_t)rBase*ldc + cBase + 1]   = v1;
            C[(size_t)(rBase+8)*ldc + cBase]   = v2;
            C[(size_t)(rBase+8)*ldc + cBase+1] = v3;
        }
    }
}

// ---------------------------------------------------------------------------
// Selective scan, software-pipelined: prefetch iteration i+1's loads before
// iteration i's shfl-reduction chain; pointer walk removes per-iter IMADs.
//   fwd: h_t = a_t h_{t-1} + u_t;           yf[t] = sum_n h_t C[t,n]
//   bwd: h_t = a_{t+1} h_{t+1} + u_t;       yb[t] = sum_n (h_t-u_t) C[t,n]
// ---------------------------------------------------------------------------
__global__ __launch_bounds__(256)
void scan_kernel(const float* __restrict__ A_log)
{
    const int w    = (blockIdx.x * 256 + threadIdx.x) >> 5;
    const int lane = threadIdx.x & 31;
    const int dir  = w >> 11;
    const int rem  = w & 2047;
    const int b    = rem >> 10;
    const int dpair= rem & 1023;
    const int half = lane >> 4;
    const int n    = lane & 15;
    const int d    = dpair*2 + half;

    const float An = -__expf(A_log[d*16 + n]);
    float h = 0.f;
    float a_prev = 0.f;

    const int t0  = dir ? 1023 : 0;
    const int sgn = dir ? -1 : 1;
    float* yout = (dir ? g_yb : g_yf) + ((size_t)b*2048 + d)*1024 + t0;
    const float* dtp = g_dt   + (size_t)b*1024*2048 + d + (size_t)t0*2048;
    const float* xp  = g_proj + (size_t)b*1024*4096 + d + (size_t)t0*4096;
    const float* bp  = g_ssm  + (size_t)b*1024*96 + 64 + n + t0*96;
    const float* cp  = bp + 16;
    const int sdt = sgn*2048, sx = sgn*4096, sb = sgn*96;

    float dtv = *dtp, x = *xp, Bv = *bp, Cv = *cp;

    #pragma unroll 4
    for (int i = 0; i < 1024; i++) {
        float dtv2 = 0.f, x2 = 0.f, Bv2 = 0.f, Cv2 = 0.f;
        if (i + 1 < 1024) {                    // prefetch next iteration
            dtp += sdt; xp += sx; bp += sb; cp += sb;
            dtv2 = *dtp; x2 = *xp; Bv2 = *bp; Cv2 = *cp;
        }
        float a = __expf(An * dtv);
        float u = dtv * Bv * x;
        float p;
        if (dir) {
            h = fmaf(a_prev, h, u);
            a_prev = a;
            p = (h - u) * Cv;
        } else {
            h = fmaf(a, h, u);
            p = h * Cv;
        }
        p += __shfl_xor_sync(0xffffffffu, p, 8);
        p += __shfl_xor_sync(0xffffffffu, p, 4);
        p += __shfl_xor_sync(0xffffffffu, p, 2);
        p += __shfl_xor_sync(0xffffffffu, p, 1);
        if (n == 0) *yout = p;
        yout += sgn;
        dtv = dtv2; x = x2; Bv = Bv2; Cv = Cv2;
    }
}

// ---------------------------------------------------------------------------
__global__ __launch_bounds__(1024)
void gate_kernel(const float* __restrict__ Dv)
{
    __shared__ float s[32][33];
    const int b  = blockIdx.z;
    const int d0 = blockIdx.y * 32;
    const int l0 = blockIdx.x * 32;
    const int tx = threadIdx.x, ty = threadIdx.y;

    size_t src = ((size_t)b*2048 + d0 + ty)*1024 + l0 + tx;
    s[ty][tx] = 1.3f * (g_yf[src] + g_yb[src]);
    __syncthreads();

    const int l = l0 + ty, d = d0 + tx;
    const size_t r = (size_t)b*1024 + l;
    float x = g_proj[r*4096 + d];
    float g = g_proj[r*4096 + 2048 + d];
    float y = s[tx][ty];
    float sil = g / (1.f + __expf(-g));
    g_so[r*2048 + d] = (y + x * Dv[d]) * sil;
}

// ---------------------------------------------------------------------------
extern "C" void kernel_launch(void* const* d_in, const int* in_sizes, int n_in,
                              void* d_out, int out_size)
{
    (void)in_sizes; (void)n_in; (void)out_size;
    const float* x     = (const float*)d_in[0];
    const float* w_in  = (const float*)d_in[1];
    const float* w_x   = (const float*)d_in[2];
    const float* w_dt  = (const float*)d_in[3];
    const float* b_dt  = (const float*)d_in[4];
    const float* A_log = (const float*)d_in[5];
    const float* Dv    = (const float*)d_in[6];
    const float* w_out = (const float*)d_in[7];
    float* out = (float*)d_out;

    float *proj, *ssm, *dtb, *so;
    cudaGetSymbolAddress((void**)&proj, g_proj);
    cudaGetSymbolAddress((void**)&ssm,  g_ssm);
    cudaGetSymbolAddress((void**)&dtb,  g_dt);
    cudaGetSymbolAddress((void**)&so,   g_so);

    // G1: proj = x @ W_in^T   (tensor cores, split-bf16)
    gemm_nt_bfsplit<<<dim3(4096/BN2, 2048/BM2), 256>>>(x, 1024, w_in, 1024,
                                                       proj, 4096, 1024);
    // G2: ssm = hidden @ W_x^T   (SIMT, ragged N=96)
    gemm_nt<0><<<dim3(1, 16), 256>>>(proj, 4096, w_x, 2048, ssm, 96,
                                     96, 2048, nullptr);
    // G3: dt = softplus(ssm[:, :64] @ W_dt^T + b)   (SIMT, K=64)
    gemm_nt<1><<<dim3(16, 16), 256>>>(ssm, 96, w_dt, 64, dtb, 2048,
                                      2048, 64, b_dt);
    // S: fwd + bwd recurrences
    scan_kernel<<<512, 256>>>(A_log);
    // T: gating + transpose
    gate_kernel<<<dim3(32, 64, 2), dim3(32, 32)>>>(Dv);
    // G4: out = scan_out @ W_out^T   (tensor cores, split-bf16)
    gemm_nt_bfsplit<<<dim3(1024/BN2, 2048/BM2), 256>>>(so, 2048, w_out, 2048,
                                                       out, 1024, 2048);
}